// round 15
// baseline (speedup 1.0000x reference)
#include <cuda_runtime.h>
#include <cstddef>

// Problem constants
#define SQ   512      // sequence length S
#define ED   512      // embedding dim E
#define HD   512      // hidden dim H
#define G4   2048     // 4*H gates
#define BSEL 63       // only batch sample 63 reaches the output
#define NVOC 32000

#define NCTA 64       // scan CTAs; each owns 8 h elements (1 per warp)
#define TPB  256      // 8 warps, all compute + poll

// Scratch (device globals; no allocation allowed)
__device__ float g_hist[SQ * HD];    // published h+2.0 per (t, element); 0 = not ready. 1 MB
__device__ float g_xg[SQ * G4];      // xg TRANSPOSED: [t][element][gate], 4 MB
__device__ int   g_tok[SQ];          // batch-63 tokens, dtype-normalized

// ---------------------------------------------------------------------------
// Kernel 0a: zero the history buffer so graph replays are deterministic.
// ---------------------------------------------------------------------------
__global__ void zero_hist_kernel() {
    int idx = blockIdx.x * blockDim.x + threadIdx.x;
    int stride = gridDim.x * blockDim.x;
    for (int i = idx; i < SQ * HD; i += stride) g_hist[i] = 0.f;
}

// ---------------------------------------------------------------------------
// Kernel 0b: normalize token dtype (int32 vs int64) and extract batch 63.
// ---------------------------------------------------------------------------
__global__ void __launch_bounds__(SQ) token_prep_kernel(const int* __restrict__ raw) {
    __shared__ int any_nz;
    const int tid = threadIdx.x;            // 0..511
    if (tid == 0) any_nz = 0;
    __syncthreads();
    if (tid < 256 && raw[2 * tid + 1] != 0) atomicExch(&any_nz, 1);
    __syncthreads();
    const bool is64 = (any_nz == 0);
    const long long idx = (long long)BSEL * SQ + tid;
    int tok = is64 ? raw[2 * idx] : raw[idx];
    tok = min(max(tok, 0), NVOC - 1);       // never IMA, even on dtype surprise
    g_tok[tid] = tok;
}

// ---------------------------------------------------------------------------
// Kernel 1: xg GEMM, output TRANSPOSED to [t][element][gate].
// ---------------------------------------------------------------------------
#define BM 64
#define BN 64
#define BK 16

__global__ void __launch_bounds__(256) xg_gemm_kernel(
    const float* __restrict__ emb,
    const float* __restrict__ Wih,
    const float* __restrict__ bih,
    const float* __restrict__ bhh)
{
    __shared__ float As[BK][BM];
    __shared__ float Bs[BK][BN];
    __shared__ int   toks[BM];

    const int bs = blockIdx.x * BM;   // s base
    const int bg = blockIdx.y * BN;   // g base
    const int tid = threadIdx.x;

    if (tid < BM) toks[tid] = g_tok[bs + tid];
    __syncthreads();

    const int tm = (tid >> 4) << 2;   // 0,4,...,60
    const int tn = (tid & 15) << 2;   // 0,4,...,60

    float acc[4][4];
    #pragma unroll
    for (int i = 0; i < 4; i++)
        #pragma unroll
        for (int j = 0; j < 4; j++) acc[i][j] = 0.f;

    for (int k0 = 0; k0 < ED; k0 += BK) {
        #pragma unroll
        for (int i = tid; i < BM * BK; i += 256) {
            int m = i >> 4, k = i & 15;
            As[k][m] = emb[(size_t)toks[m] * ED + k0 + k];
        }
        #pragma unroll
        for (int i = tid; i < BN * BK; i += 256) {
            int n = i >> 4, k = i & 15;
            Bs[k][n] = Wih[(size_t)(bg + n) * ED + k0 + k];
        }
        __syncthreads();
        #pragma unroll
        for (int k = 0; k < BK; k++) {
            float4 a = *(const float4*)&As[k][tm];
            float4 b = *(const float4*)&Bs[k][tn];
            float av[4] = {a.x, a.y, a.z, a.w};
            float bv[4] = {b.x, b.y, b.z, b.w};
            #pragma unroll
            for (int i = 0; i < 4; i++)
                #pragma unroll
                for (int j = 0; j < 4; j++)
                    acc[i][j] = fmaf(av[i], bv[j], acc[i][j]);
        }
        __syncthreads();
    }

    #pragma unroll
    for (int i = 0; i < 4; i++) {
        int s = bs + tm + i;
        #pragma unroll
        for (int j = 0; j < 4; j++) {
            int g = bg + tn + j;
            int e = g & (HD - 1), q = g >> 9;
            g_xg[(size_t)s * G4 + (e << 2) + q] = acc[i][j] + bih[g] + bhh[g];
        }
    }
}

// ---------------------------------------------------------------------------
// Kernel 2: persistent LSTM scan, batch element 63 only.
// 64 CTAs x 256 threads (8 warps). Warp w owns element hi = 8*cta + w:
//   - all 4 gate dots in-warp (64 FFMA/lane, W_hh rows in 64 regs)
//   - one 4-value butterfly reduce
//   - lane 0: hardware tanh.approx activations (sigmoid via tanh identity),
//     c/h update, volatile publish of h+2.0f (never zero bits)
// Then ALL warps poll g_hist[t] (v2 per lane, post-publish only — the R8
// timing that avoided spin interference) and stage h-2 into the next-parity
// smem buffer. ONE __syncthreads per step. xg biases are software-pipelined
// one step ahead so their load never sits on the serial chain.
// ---------------------------------------------------------------------------
__device__ __forceinline__ float tanh_hw(float x) {
    float y;
    asm("tanh.approx.f32 %0, %1;" : "=f"(y) : "f"(x));
    return y;
}
__device__ __forceinline__ float sigmoid_hw(float x) {
    return fmaf(0.5f, tanh_hw(0.5f * x), 0.5f);
}

__global__ void __launch_bounds__(TPB, 1) lstm_scan_kernel(
    const float* __restrict__ h0,
    const float* __restrict__ c0,
    const float* __restrict__ Whh)
{
    __shared__ float h_sm[2][HD];       // parity double-buffered current h (4 KB)

    const int cta = blockIdx.x;         // 0..63
    const int tid = threadIdx.x;
    const int w = tid >> 5;             // warp 0..7
    const int l = tid & 31;
    const int hi = (cta << 3) + w;      // owned global h element

    // Weights: gate q row = q*512 + hi; lane l covers elements a*128 + l*4 + j.
    float wt[4][16];
    #pragma unroll
    for (int q = 0; q < 4; q++) {
        const float* row = Whh + ((size_t)((q << 9) + hi) << 9);
        #pragma unroll
        for (int a = 0; a < 4; a++) {
            float4 v = *(const float4*)&row[(a << 7) + (l << 2)];
            wt[q][a * 4 + 0] = v.x; wt[q][a * 4 + 1] = v.y;
            wt[q][a * 4 + 2] = v.z; wt[q][a * 4 + 3] = v.w;
        }
    }

    float creg = 0.f;
    float4 xg_cur = make_float4(0.f, 0.f, 0.f, 0.f);
    if (l == 0) {
        creg = c0[(size_t)BSEL * HD + hi];
        xg_cur = *(const float4*)&g_xg[(size_t)0 + (hi << 2)];   // step 0 biases
    }

    // Seed h_sm[0] with h0[0, 63, :] (two elements per thread)
    h_sm[0][tid]       = h0[(size_t)BSEL * HD + tid];
    h_sm[0][tid + 256] = h0[(size_t)BSEL * HD + tid + 256];
    __syncthreads();

    for (int t = 0; t < SQ; t++) {
        // ---- compute: 4 dots of length 512 (h from smem, W from regs) ----
        const float* hb = h_sm[t & 1];
        float hreg[16];
        #pragma unroll
        for (int a = 0; a < 4; a++) {
            float4 v = *(const float4*)&hb[(a << 7) + (l << 2)];
            hreg[a * 4 + 0] = v.x; hreg[a * 4 + 1] = v.y;
            hreg[a * 4 + 2] = v.z; hreg[a * 4 + 3] = v.w;
        }
        float s0 = xg_cur.x, s1 = xg_cur.y, s2 = xg_cur.z, s3 = xg_cur.w;
        #pragma unroll
        for (int i = 0; i < 16; i++) {
            s0 = fmaf(wt[0][i], hreg[i], s0);
            s1 = fmaf(wt[1][i], hreg[i], s1);
            s2 = fmaf(wt[2][i], hreg[i], s2);
            s3 = fmaf(wt[3][i], hreg[i], s3);
        }
        #pragma unroll
        for (int off = 16; off; off >>= 1) {
            s0 += __shfl_xor_sync(0xffffffffu, s0, off);
            s1 += __shfl_xor_sync(0xffffffffu, s1, off);
            s2 += __shfl_xor_sync(0xffffffffu, s2, off);
            s3 += __shfl_xor_sync(0xffffffffu, s3, off);
        }

        // ---- lane 0: hardware-tanh activations + publish ----
        if (l == 0) {
            float iv = sigmoid_hw(s0);
            float fv = sigmoid_hw(s1);
            float gv = tanh_hw(s2);
            float ov = sigmoid_hw(s3);
            creg = fv * creg + iv * gv;
            float hv = ov * tanh_hw(creg);
            float pub = hv + 2.0f;          // in (1,3): never zero bits
            float* dst = g_hist + (t << 9) + hi;
            asm volatile("st.volatile.global.f32 [%0], %1;"
                         :: "l"(dst), "f"(pub) : "memory");
            // prefetch next step's xg biases (off the serial chain)
            if (t + 1 < SQ)
                xg_cur = *(const float4*)&g_xg[((size_t)(t + 1) << 11) + (hi << 2)];
        }

        // ---- poll h(t) and stage into next-parity smem (post-publish only) ----
        if (t + 1 < SQ) {
            const int base = (w << 6) + (l << 1);       // 2 words per lane
            const float* p = g_hist + (t << 9) + base;
            unsigned a, b;
            for (;;) {
                asm volatile("ld.volatile.global.v2.u32 {%0,%1}, [%2];"
                             : "=r"(a), "=r"(b) : "l"(p));
                if (a != 0u && b != 0u) break;
            }
            float* q = &h_sm[(t + 1) & 1][base];
            q[0] = __uint_as_float(a) - 2.0f;
            q[1] = __uint_as_float(b) - 2.0f;
        }
        __syncthreads();
    }
}

// ---------------------------------------------------------------------------
// Kernel 3: out[s,t] = (hist[s,:]-2) . W_lin[t,:] + b_lin[t]   (1024 outputs)
// ---------------------------------------------------------------------------
__global__ void __launch_bounds__(256) final_linear_kernel(
    const float* __restrict__ Wlin,
    const float* __restrict__ blin,
    float* __restrict__ out)
{
    const int w = threadIdx.x >> 5, l = threadIdx.x & 31;
    const int wi = blockIdx.x * 8 + w;     // 0..1023
    const int s = wi >> 1, tt = wi & 1;
    float acc = 0.f;
    #pragma unroll
    for (int e = l; e < HD; e += 32) {
        float hv = g_hist[(size_t)s * HD + e] - 2.0f;
        acc = fmaf(hv, Wlin[(size_t)tt * HD + e], acc);
    }
    #pragma unroll
    for (int off = 16; off; off >>= 1) acc += __shfl_xor_sync(0xffffffffu, acc, off);
    if (l == 0) out[s * 2 + tt] = acc + blin[tt];
}

// ---------------------------------------------------------------------------
extern "C" void kernel_launch(void* const* d_in, const int* in_sizes, int n_in,
                              void* d_out, int out_size)
{
    const int*   sent = (const int*)d_in[0];            // (64,512) int32/int64 words
    const float* h0   = (const float*)d_in[1];          // (1,64,512)
    const float* c0   = (const float*)d_in[2];          // (1,64,512)
    const float* emb  = (const float*)d_in[3];          // (32000,512)
    const float* Wih  = (const float*)d_in[4];          // (2048,512)
    const float* Whh  = (const float*)d_in[5];          // (2048,512)
    const float* bih  = (const float*)d_in[6];          // (2048,)
    const float* bhh  = (const float*)d_in[7];          // (2048,)
    const float* Wlin = (const float*)d_in[8];          // (2,512)
    const float* blin = (const float*)d_in[9];          // (2,)
    float* out = (float*)d_out;                         // (512,2)

    zero_hist_kernel<<<256, 256>>>();
    token_prep_kernel<<<1, SQ>>>(sent);
    xg_gemm_kernel<<<dim3(SQ / BM, G4 / BN), 256>>>(emb, Wih, bih, bhh);
    lstm_scan_kernel<<<NCTA, TPB>>>(h0, c0, Whh);
    final_linear_kernel<<<128, 256>>>(Wlin, blin, out);
}

// round 16
// speedup vs baseline: 1.1914x; 1.1914x over previous
#include <cuda_runtime.h>
#include <cstddef>

// Problem constants
#define SQ   512      // sequence length S
#define ED   512      // embedding dim E
#define HD   512      // hidden dim H
#define G4   2048     // 4*H gates
#define BSEL 63       // only batch sample 63 reaches the output
#define NVOC 32000

#define NCTA 64       // scan CTAs; each owns 8 h elements
#define TPB  512      // 16 warps

// Scratch (device globals; no allocation allowed)
__device__ float g_hist[SQ * HD];    // published h+2.0 per (t, element); 0 = not ready. 1 MB
__device__ float g_xg[SQ * G4];      // xg TRANSPOSED: [t][element][gate], 4 MB
__device__ int   g_tok[SQ];          // batch-63 tokens, dtype-normalized

// ---------------------------------------------------------------------------
// Kernel 0a: zero the history buffer so graph replays are deterministic.
// ---------------------------------------------------------------------------
__global__ void zero_hist_kernel() {
    int idx = blockIdx.x * blockDim.x + threadIdx.x;
    int stride = gridDim.x * blockDim.x;
    for (int i = idx; i < SQ * HD; i += stride) g_hist[i] = 0.f;
}

// ---------------------------------------------------------------------------
// Kernel 0b: normalize token dtype (int32 vs int64) and extract batch 63.
// ---------------------------------------------------------------------------
__global__ void __launch_bounds__(SQ) token_prep_kernel(const int* __restrict__ raw) {
    __shared__ int any_nz;
    const int tid = threadIdx.x;            // 0..511
    if (tid == 0) any_nz = 0;
    __syncthreads();
    if (tid < 256 && raw[2 * tid + 1] != 0) atomicExch(&any_nz, 1);
    __syncthreads();
    const bool is64 = (any_nz == 0);
    const long long idx = (long long)BSEL * SQ + tid;
    int tok = is64 ? raw[2 * idx] : raw[idx];
    tok = min(max(tok, 0), NVOC - 1);       // never IMA, even on dtype surprise
    g_tok[tid] = tok;
}

// ---------------------------------------------------------------------------
// Kernel 1: xg GEMM, output TRANSPOSED to [t][element][gate].
// ---------------------------------------------------------------------------
#define BM 64
#define BN 64
#define BK 16

__global__ void __launch_bounds__(256) xg_gemm_kernel(
    const float* __restrict__ emb,
    const float* __restrict__ Wih,
    const float* __restrict__ bih,
    const float* __restrict__ bhh)
{
    __shared__ float As[BK][BM];
    __shared__ float Bs[BK][BN];
    __shared__ int   toks[BM];

    const int bs = blockIdx.x * BM;   // s base
    const int bg = blockIdx.y * BN;   // g base
    const int tid = threadIdx.x;

    if (tid < BM) toks[tid] = g_tok[bs + tid];
    __syncthreads();

    const int tm = (tid >> 4) << 2;   // 0,4,...,60
    const int tn = (tid & 15) << 2;   // 0,4,...,60

    float acc[4][4];
    #pragma unroll
    for (int i = 0; i < 4; i++)
        #pragma unroll
        for (int j = 0; j < 4; j++) acc[i][j] = 0.f;

    for (int k0 = 0; k0 < ED; k0 += BK) {
        #pragma unroll
        for (int i = tid; i < BM * BK; i += 256) {
            int m = i >> 4, k = i & 15;
            As[k][m] = emb[(size_t)toks[m] * ED + k0 + k];
        }
        #pragma unroll
        for (int i = tid; i < BN * BK; i += 256) {
            int n = i >> 4, k = i & 15;
            Bs[k][n] = Wih[(size_t)(bg + n) * ED + k0 + k];
        }
        __syncthreads();
        #pragma unroll
        for (int k = 0; k < BK; k++) {
            float4 a = *(const float4*)&As[k][tm];
            float4 b = *(const float4*)&Bs[k][tn];
            float av[4] = {a.x, a.y, a.z, a.w};
            float bv[4] = {b.x, b.y, b.z, b.w};
            #pragma unroll
            for (int i = 0; i < 4; i++)
                #pragma unroll
                for (int j = 0; j < 4; j++)
                    acc[i][j] = fmaf(av[i], bv[j], acc[i][j]);
        }
        __syncthreads();
    }

    #pragma unroll
    for (int i = 0; i < 4; i++) {
        int s = bs + tm + i;
        #pragma unroll
        for (int j = 0; j < 4; j++) {
            int g = bg + tn + j;
            int e = g & (HD - 1), q = g >> 9;
            g_xg[(size_t)s * G4 + (e << 2) + q] = acc[i][j] + bih[g] + bhh[g];
        }
    }
}

// ---------------------------------------------------------------------------
// Kernel 2: persistent LSTM scan, batch element 63 only.  (R8 frozen base.)
// 64 CTAs x 512 threads (16 warps). CTA c owns h elements [8c, 8c+8).
// Warp w computes 2 of the CTA's 32 gate dots (weights in 32 regs/lane);
// warp0 lanes 0-7 do hw-tanh activations and publish h+2 for all 8 elements
// in ONE coalesced 32B store.
// Deltas vs R8: (1) publish is st.relaxed.gpu while polls stay ld.volatile —
// isolates the store-visibility path that R10 confounded; (2) tanh.approx
// tail; (3) offset-fold: the exchanged value is h+2 end-to-end, with
// -2*rowsum(W_row) folded into each dot's xg seed, so staging is a raw copy.
// ---------------------------------------------------------------------------
__device__ __forceinline__ float tanh_hw(float x) {
    float y;
    asm("tanh.approx.f32 %0, %1;" : "=f"(y) : "f"(x));
    return y;
}
__device__ __forceinline__ float sigmoid_hw(float x) {
    return fmaf(0.5f, tanh_hw(0.5f * x), 0.5f);
}

__global__ void __launch_bounds__(TPB, 1) lstm_scan_kernel(
    const float* __restrict__ h0,
    const float* __restrict__ c0,
    const float* __restrict__ Whh)
{
    __shared__ float h_sm[2][HD];       // parity double-buffered h+2 (4 KB)
    __shared__ float gexch[32];         // final gate pre-activations, q*8+e

    const int cta = blockIdx.x;         // 0..63
    const int tid = threadIdx.x;
    const int w = tid >> 5;             // warp 0..15
    const int l = tid & 31;

    // Warp w owns dots d0=2w, d1=2w+1; d = q*8+e (q=gate 0..3, e=local elem 0..7)
    const int d0 = 2 * w, d1 = 2 * w + 1;
    const int r0 = ((d0 >> 3) << 9) + (cta << 3) + (d0 & 7);   // W_hh row for d0
    const int r1 = ((d1 >> 3) << 9) + (cta << 3) + (d1 & 7);
    float wt0[16], wt1[16];
    #pragma unroll
    for (int a = 0; a < 4; a++) {
        float4 v = *(const float4*)&Whh[((size_t)r0 << 9) + (a << 7) + (l << 2)];
        wt0[a * 4 + 0] = v.x; wt0[a * 4 + 1] = v.y;
        wt0[a * 4 + 2] = v.z; wt0[a * 4 + 3] = v.w;
        float4 u = *(const float4*)&Whh[((size_t)r1 << 9) + (a << 7) + (l << 2)];
        wt1[a * 4 + 0] = u.x; wt1[a * 4 + 1] = u.y;
        wt1[a * 4 + 2] = u.z; wt1[a * 4 + 3] = u.w;
    }

    // Row sums (x2) for the offset-fold: dot(W, h+2) - 2*sum(W) = dot(W, h).
    float rs0 = 0.f, rs1 = 0.f;
    #pragma unroll
    for (int i = 0; i < 16; i++) { rs0 += wt0[i]; rs1 += wt1[i]; }
    #pragma unroll
    for (int off = 16; off; off >>= 1) {
        rs0 += __shfl_xor_sync(0xffffffffu, rs0, off);
        rs1 += __shfl_xor_sync(0xffffffffu, rs1, off);
    }
    rs0 *= 2.f; rs1 *= 2.f;

    // xg addresses for this warp's two dots (lane 0 uses them)
    const int xga_off = (((cta << 3) + (d0 & 7)) << 2) + (d0 >> 3);
    const int xgb_off = (((cta << 3) + (d1 & 7)) << 2) + (d1 >> 3);

    float creg = 0.f;
    if (w == 0 && l < 8) creg = c0[(size_t)BSEL * HD + (cta << 3) + l];

    // Seed h_sm[0] with h0[0, 63, :] + 2 (offset domain)
    h_sm[0][tid] = h0[(size_t)BSEL * HD + tid] + 2.0f;
    __syncthreads();

    for (int t = 0; t < SQ; t++) {
        // Lane 0: prefetch this step's two xg biases before the poll (overlapped).
        float xga = 0.f, xgb = 0.f;
        if (l == 0) {
            xga = g_xg[((size_t)t << 11) + xga_off];
            xgb = g_xg[((size_t)t << 11) + xgb_off];
        }

        if (t > 0) {
            // Warp w polls its disjoint 32-element chunk of h(t-1), 1 word/lane.
            const float* p = g_hist + ((t - 1) << 9) + (w << 5) + l;
            unsigned a;
            for (;;) {
                asm volatile("ld.volatile.global.u32 %0, [%1];" : "=r"(a) : "l"(p));
                if (__all_sync(0xffffffffu, a != 0u)) break;
            }
            h_sm[t & 1][(w << 5) + l] = __uint_as_float(a);  // raw h+2, no debias
        }
        __syncthreads();

        // Two 512-length dots (h+2 from smem, W from registers).
        const float* hb = h_sm[t & 1];
        float hreg[16];
        #pragma unroll
        for (int a = 0; a < 4; a++) {
            float4 v = *(const float4*)&hb[(a << 7) + (l << 2)];
            hreg[a * 4 + 0] = v.x; hreg[a * 4 + 1] = v.y;
            hreg[a * 4 + 2] = v.z; hreg[a * 4 + 3] = v.w;
        }
        float s0 = (l == 0) ? (xga - rs0) : 0.f;   // bias + offset-fold, once
        float s1 = (l == 0) ? (xgb - rs1) : 0.f;
        #pragma unroll
        for (int i = 0; i < 16; i++) {
            s0 = fmaf(wt0[i], hreg[i], s0);
            s1 = fmaf(wt1[i], hreg[i], s1);
        }
        #pragma unroll
        for (int off = 16; off; off >>= 1) {
            s0 += __shfl_xor_sync(0xffffffffu, s0, off);
            s1 += __shfl_xor_sync(0xffffffffu, s1, off);
        }
        if (l == 0) { gexch[d0] = s0; gexch[d1] = s1; }
        __syncthreads();

        // Warp0 lanes 0-7: hw-tanh activations + ONE coalesced 32B publish.
        if (w == 0 && l < 8) {
            float iv = sigmoid_hw(gexch[l]);
            float fv = sigmoid_hw(gexch[8 + l]);
            float gv = tanh_hw(gexch[16 + l]);
            float ov = sigmoid_hw(gexch[24 + l]);
            creg = fv * creg + iv * gv;
            float hv = ov * tanh_hw(creg);
            float pub = hv + 2.0f;          // in (1,3): never zero bits
            float* dst = g_hist + (t << 9) + (cta << 3) + l;
            asm volatile("st.relaxed.gpu.global.f32 [%0], %1;"
                         :: "l"(dst), "f"(pub) : "memory");
        }
        // h_sm is parity double-buffered; the two barriers above bound skew.
    }
}

// ---------------------------------------------------------------------------
// Kernel 3: out[s,t] = (hist[s,:]-2) . W_lin[t,:] + b_lin[t]   (1024 outputs)
// ---------------------------------------------------------------------------
__global__ void __launch_bounds__(256) final_linear_kernel(
    const float* __restrict__ Wlin,
    const float* __restrict__ blin,
    float* __restrict__ out)
{
    const int w = threadIdx.x >> 5, l = threadIdx.x & 31;
    const int wi = blockIdx.x * 8 + w;     // 0..1023
    const int s = wi >> 1, tt = wi & 1;
    float acc = 0.f;
    #pragma unroll
    for (int e = l; e < HD; e += 32) {
        float hv = g_hist[(size_t)s * HD + e] - 2.0f;
        acc = fmaf(hv, Wlin[(size_t)tt * HD + e], acc);
    }
    #pragma unroll
    for (int off = 16; off; off >>= 1) acc += __shfl_xor_sync(0xffffffffu, acc, off);
    if (l == 0) out[s * 2 + tt] = acc + blin[tt];
}

// ---------------------------------------------------------------------------
extern "C" void kernel_launch(void* const* d_in, const int* in_sizes, int n_in,
                              void* d_out, int out_size)
{
    const int*   sent = (const int*)d_in[0];            // (64,512) int32/int64 words
    const float* h0   = (const float*)d_in[1];          // (1,64,512)
    const float* c0   = (const float*)d_in[2];          // (1,64,512)
    const float* emb  = (const float*)d_in[3];          // (32000,512)
    const float* Wih  = (const float*)d_in[4];          // (2048,512)
    const float* Whh  = (const float*)d_in[5];          // (2048,512)
    const float* bih  = (const float*)d_in[6];          // (2048,)
    const float* bhh  = (const float*)d_in[7];          // (2048,)
    const float* Wlin = (const float*)d_in[8];          // (2,512)
    const float* blin = (const float*)d_in[9];          // (2,)
    float* out = (float*)d_out;                         // (512,2)

    zero_hist_kernel<<<256, 256>>>();
    token_prep_kernel<<<1, SQ>>>(sent);
    xg_gemm_kernel<<<dim3(SQ / BM, G4 / BN), 256>>>(emb, Wih, bih, bhh);
    lstm_scan_kernel<<<NCTA, TPB>>>(h0, c0, Whh);
    final_linear_kernel<<<128, 256>>>(Wlin, blin, out);
}